// round 13
// baseline (speedup 1.0000x reference)
#include <cuda_runtime.h>
#include <math.h>

#define NLAT 128
#define NLON 256
#define LMAX 50
#define MMAX 50
#define NPTS 2048
#define NB   2
#define MG   (NLAT*NLON)
#define NBT  32
#define NBP  64
#define NBINS (NBT*NBP)
#define PI_F 3.14159265358979323846f
#define H_BIN (PI_F/32.0f)
#define INVH  (32.0f/PI_F)
#define CAP   1536
#define NBLK  512
#define KINF  0x7F7FFFFFu
#define FIDX(n) ((n) + ((n) >> 5))

// ---- device scratch (globals; zero-init at load) ----
__device__ float4 g_sorted[4][NPTS];
__device__ int    g_binstart[4][NBINS + 1];
__device__ float  g_grid[4][MG];
__device__ float  g_pctw[MMAX][LMAX][NLAT];
__device__ float  g_rexf[4][MMAX][NLAT];
__device__ float  g_part[NB * LMAX * MMAX];   // l<m entries stay 0 forever
__device__ int    g_barc[3 * 32];
__device__ int    g_done;

union Smem {
    struct { float4 pts[NPTS]; int cnt[NBINS]; int wsum[8]; } prep;   // ~41KB
    struct { float4 cand[CAP]; int rowoff[12]; int rowsrc[12];
             int sbs[8][22]; } it;                                    // ~25KB
    struct { float row[NLON]; float fold[136]; } rx;
    float red[64];
};

__device__ __forceinline__ void gbar(int id) {
    __syncthreads();
    if (threadIdx.x == 0) {
        __threadfence();
        atomicAdd(&g_barc[id * 32], 1);
        while (*(volatile int*)&g_barc[id * 32] < NBLK) __nanosleep(64);
        __threadfence();
        int l = atomicAdd(&g_barc[id * 32 + 1], 1);
        if (l == NBLK - 1) {
            *(volatile int*)&g_barc[id * 32]     = 0;
            *(volatile int*)&g_barc[id * 32 + 1] = 0;
            __threadfence();
        }
    }
    __syncthreads();
}

__device__ __forceinline__ int bin_of(float th, float ph) {
    int bt = (int)(th * INVH);
    int bp = (int)((ph + PI_F) * INVH);
    bt = min(max(bt, 0), NBT - 1);
    bp = min(max(bp, 0), NBP - 1);
    return bt * NBP + bp;
}

__device__ __forceinline__ void ins3(unsigned& k0, unsigned& k1, unsigned& k2, unsigned key) {
    unsigned t  = max(k0, key); k0 = min(k0, key);
    unsigned t2 = max(k1, t);   k1 = min(k1, t);
    k2 = min(k2, t2);
}

__global__ void __launch_bounds__(256, 4)
k_mega(const float* __restrict__ pred, const float* __restrict__ tgt,
       float* __restrict__ out) {
    __shared__ Smem sm;
    __shared__ int s_last;
    int bid  = blockIdx.x;
    int tid  = threadIdx.x;
    int lane = tid & 31;
    int wid  = tid >> 5;

    // ================= Phase A: prep (blocks 0-3) + pctw (4-28) =============
    if (bid < 4) {
        int cb = bid;
        int t = cb >> 1, b = cb & 1;
        const float* src = (t ? tgt : pred) + (size_t)b * NPTS * 3;
        for (int i = tid; i < NBINS; i += 256) sm.prep.cnt[i] = 0;
        __syncthreads();
        for (int i = tid; i < NPTS; i += 256) {
            float x = src[3 * i], y = src[3 * i + 1], z = src[3 * i + 2];
            float r   = sqrtf(x * x + y * y + z * z);
            float pn1 = sqrtf(y * y + z * z);
            float th  = acosf(fminf(fmaxf(x / r,   -1.0f), 1.0f));
            float a   = acosf(fminf(fmaxf(y / pn1, -1.0f), 1.0f));
            float ph  = ((z < 0.0f) ? (2.0f * PI_F - a) : a) - PI_F;
            float4 o; o.x = th; o.y = ph; o.z = r; o.w = 0.0f;
            sm.prep.pts[i] = o;
            atomicAdd(&sm.prep.cnt[bin_of(th, ph)], 1);
        }
        __syncthreads();
        int base = tid * 8;
        int local[8]; int s = 0;
#pragma unroll
        for (int j = 0; j < 8; ++j) { local[j] = s; s += sm.prep.cnt[base + j]; }
        int v = s;
#pragma unroll
        for (int o = 1; o < 32; o <<= 1) {
            int u = __shfl_up_sync(0xffffffffu, v, o);
            if (lane >= o) v += u;
        }
        if (lane == 31) sm.prep.wsum[wid] = v;
        __syncthreads();
        if (tid == 0) {
            int a = 0;
            for (int j = 0; j < 8; ++j) { int x = sm.prep.wsum[j]; sm.prep.wsum[j] = a; a += x; }
        }
        __syncthreads();
        int excl = v - s + sm.prep.wsum[wid];
#pragma unroll
        for (int j = 0; j < 8; ++j) {
            int off = excl + local[j];
            sm.prep.cnt[base + j] = off;
            g_binstart[cb][base + j] = off;
        }
        if (tid == 0) g_binstart[cb][NBINS] = NPTS;
        __syncthreads();
        for (int i = tid; i < NPTS; i += 256) {
            float4 p = sm.prep.pts[i];
            int pos = atomicAdd(&sm.prep.cnt[bin_of(p.x, p.y)], 1);
            g_sorted[cb][pos] = p;
        }
    } else if (bid < 29) {
        int m = (bid - 4) * 2 + (tid >> 7);
        int k = tid & 127;
        if (m < MMAX) {
            float theta = PI_F * (float)k / (float)(NLAT - 1);
            float cost  = cosf(theta);
            float sint  = sqrtf(fmaxf(1.0f - cost * cost, 0.0f));
            float c2  = cosf(2.0f * theta);
            float tc2 = 2.0f * c2;
            float cm1 = 1.0f, cj = c2;
            float v = 0.0f;
#pragma unroll 7
            for (int j = 1; j <= 63; ++j) {
                v = fmaf(cj, 2.0f / (4.0f * (float)j * (float)j - 1.0f), v);
                float cn = fmaf(tc2, cj, -cm1);
                cm1 = cj; cj = cn;
            }
            float w = (2.0f / 127.0f) * (1.0f - v);
            if (k == 0 || k == 127) w *= 0.5f;
            float pmm = sqrtf(1.0f / (4.0f * PI_F));
            for (int mm = 1; mm <= m; ++mm)
                pmm = -pmm * sqrtf((2.0f * mm + 1.0f) / (2.0f * mm)) * sint;
            for (int l = 0; l < m; ++l) g_pctw[m][l][k] = 0.0f;
            g_pctw[m][m][k] = pmm * w;
            if (m + 1 < LMAX) {
                float plm2 = pmm;
                float plm1 = sqrtf(2.0f * m + 3.0f) * cost * pmm;
                g_pctw[m][m + 1][k] = plm1 * w;
                for (int l = m + 2; l < LMAX; ++l) {
                    float fl = (float)l, fm = (float)m;
                    float a = sqrtf((4.0f * fl * fl - 1.0f) / (fl * fl - fm * fm));
                    float bq = sqrtf(((2.0f * fl + 1.0f) * (fl - 1.0f + fm) * (fl - 1.0f - fm)) /
                                     ((2.0f * fl - 3.0f) * (fl * fl - fm * fm)));
                    float pl = a * cost * plm1 - bq * plm2;
                    g_pctw[m][l][k] = pl * w;
                    plm2 = plm1; plm1 = pl;
                }
            }
        }
    }
    gbar(0);

    // ================= Phase B: 3-NN interp, per-thread bin windows =========
    {
        int cb  = bid >> 7;
        int rem = bid & 127;
        int ty8 = rem >> 4, tx16 = rem & 15;
        int bt0 = ty8 * 4, bp0 = tx16 * 4;
        bool pole = (ty8 == 0) || (ty8 == 7);

        int irow = ty8 * 16 + (tid >> 4);
        int icol = tx16 * 16 + (tid & 15);
        float gth = (float)irow * (PI_F / NLAT);
        float gph = (float)(icol - NLAT) * (PI_F / NLAT);
        float gpp = gph + PI_F;

        int ht0, ht1, hp0, hp1;
        if (pole) {
            ht0 = (ty8 == 0) ? 0 : 25;
            ht1 = (ty8 == 0) ? 6 : 31;
            hp0 = max(bp0 - 8, 0);
            hp1 = min(bp0 + 11, NBP - 1);
        } else {
            ht0 = max(bt0 - 2, 0); ht1 = min(bt0 + 5, NBT - 1);
            hp0 = max(bp0 - 2, 0); hp1 = min(bp0 + 5, NBP - 1);
        }
        int nrows = ht1 - ht0 + 1;
        int ncols = hp1 - hp0 + 1;
        if (tid < nrows) {
            int s = g_binstart[cb][(ht0 + tid) * NBP + hp0];
            int e = g_binstart[cb][(ht0 + tid) * NBP + hp1 + 1];
            sm.it.rowsrc[tid] = s;
            sm.it.rowoff[tid] = e - s;
        }
        __syncthreads();
        if (tid == 0) {
            int off = 0;
            for (int r = 0; r < nrows; ++r) {
                int len = sm.it.rowoff[r];
                sm.it.rowoff[r] = off;
                off += len;
            }
            sm.it.rowoff[nrows] = off;
        }
        __syncthreads();
        int ncand = sm.it.rowoff[nrows];
        bool ovf = ncand > CAP;
        if (!ovf) {
            for (int r = 0; r < nrows; ++r) {
                int o0 = sm.it.rowoff[r], len = sm.it.rowoff[r + 1] - o0, s0 = sm.it.rowsrc[r];
                for (int i = tid; i < len; i += 256) {
                    float4 p = g_sorted[cb][s0 + i];
                    p.w = __uint_as_float((unsigned)(s0 + i));
                    sm.it.cand[o0 + i] = p;
                }
            }
        }
        // per-bin local segment boundaries: sbs[r][c], c=0..ncols
        for (int i = tid; i < nrows * (ncols + 1); i += 256) {
            int r = i / (ncols + 1), c = i - r * (ncols + 1);
            sm.it.sbs[r][c] = g_binstart[cb][(ht0 + r) * NBP + hp0 + c]
                              - sm.it.rowsrc[r] + sm.it.rowoff[r];
        }
        __syncthreads();

        int bt = irow >> 2, bp = icol >> 2;
        int yw0, yw1, w;
        if (pole) {
            yw0 = ht0; yw1 = ht1;
            w = (fminf(gth, PI_F - gth) < 0.25f) ? 8 : 4;
        } else {
            yw0 = max(bt - 2, 0); yw1 = min(bt + 2, NBT - 1);
            w = 2;
        }
        int xw0 = max(bp - w, 0), xw1 = min(bp + w, NBP - 1);
        float mT = (yw0 == 0)       ? 1e9f : gth - (float)yw0 * H_BIN;
        float mB = (yw1 == NBT - 1) ? 1e9f : (float)(yw1 + 1) * H_BIN - gth;
        float mL = (xw0 == 0)       ? 1e9f : gpp - (float)xw0 * H_BIN;
        float mR = (xw1 == NBP - 1) ? 1e9f : (float)(xw1 + 1) * H_BIN - gpp;
        float margin = fminf(fminf(mT, mB), fminf(mL, mR));

        unsigned k0 = KINF, k1 = KINF, k2 = KINF;
        if (!ovf) {
            for (int y = yw0; y <= yw1; ++y) {
                int lr = y - ht0;
                int s = sm.it.sbs[lr][xw0 - hp0];
                int e = sm.it.sbs[lr][xw1 + 1 - hp0];
                for (int i = s; i < e; ++i) {
                    float4 p = sm.it.cand[i];
                    float dx = gth - p.x, dy = gph - p.y;
                    float d = fmaf(dx, dx, dy * dy);
                    unsigned key = (__float_as_uint(d) & 0xFFFFF800u) | __float_as_uint(p.w);
                    ins3(k0, k1, k2, key);
                }
            }
        }

        float d2k = __uint_as_float(k2 & 0xFFFFF800u);
        if (ovf || d2k > margin * margin) {
            int st0 = ovf ? 1000 : yw0, st1 = ovf ? -1 : yw1;
            int sp0 = ovf ? 1000 : xw0, sp1 = ovf ? -1 : xw1;
            int cbt = min(bt, NBT - 1), cbp = min(bp, NBP - 1);
            for (int R = 0; R <= 64; ++R) {
                if (R > 0) {
                    float lb = (float)(R - 1) * H_BIN;
                    d2k = __uint_as_float(k2 & 0xFFFFF800u);
                    if (d2k <= lb * lb) break;
                }
                int t0 = max(cbt - R, 0), t1 = min(cbt + R, NBT - 1);
                int p0 = max(cbp - R, 0), p1 = min(cbp + R, NBP - 1);
                for (int y = t0; y <= t1; ++y) {
                    bool full = (R == 0) || (y == cbt - R) || (y == cbt + R);
                    int xs = full ? p0 : (cbp - R);
                    int xe = full ? p1 : (cbp + R);
                    int xstep = full ? 1 : (2 * R);
                    for (int x = xs; x <= xe; x += xstep) {
                        if (x < 0 || x > NBP - 1) continue;
                        if (y >= st0 && y <= st1 && x >= sp0 && x <= sp1) continue;
                        int bi = y * NBP + x;
                        int s0 = g_binstart[cb][bi], s1 = g_binstart[cb][bi + 1];
                        for (int i = s0; i < s1; ++i) {
                            float4 p = g_sorted[cb][i];
                            float dx = gth - p.x, dy = gph - p.y;
                            float d = fmaf(dx, dx, dy * dy);
                            unsigned key = (__float_as_uint(d) & 0xFFFFF800u) | (unsigned)i;
                            ins3(k0, k1, k2, key);
                        }
                    }
                }
            }
        }

        float4 q0 = g_sorted[cb][k0 & 0x7FFu];
        float4 q1 = g_sorted[cb][k1 & 0x7FFu];
        float4 q2 = g_sorted[cb][k2 & 0x7FFu];
        float dx, dy;
        dx = gth - q0.x; dy = gph - q0.y; float e0 = fmaf(dx, dx, dy * dy);
        dx = gth - q1.x; dy = gph - q1.y; float e1 = fmaf(dx, dx, dy * dy);
        dx = gth - q2.x; dy = gph - q2.y; float e2 = fmaf(dx, dx, dy * dy);
        float s = e0 + e1 + e2;
        g_grid[cb][irow * NLON + icol] = (e0 * q0.z + e1 * q1.z + e2 * q2.z) / s;
    }
    gbar(1);

    // ================= Phase C: DFT via fold + Chebyshev ====================
    {
        int combo = bid >> 7;
        int k     = bid & 127;
        sm.rx.row[tid] = g_grid[combo][k * NLON + tid];
        __syncthreads();
        if (tid == 0)            sm.rx.fold[FIDX(0)] = sm.rx.row[0];
        else if (tid < 128)      sm.rx.fold[FIDX(tid)] = sm.rx.row[tid] + sm.rx.row[256 - tid];
        __syncthreads();

        int m = tid >> 2, q = tid & 3;
        float am = (PI_F / 128.0f) * (float)m;
        int n0 = q * 32;
        float s0, c0, s1, c1;
        sincosf(am * (float)n0, &s0, &c0);
        sincosf(am, &s1, &c1);
        float c2 = fmaf(2.0f * c1, c1, -1.0f);
        float s2 = 2.0f * s1 * c1;
        float cE  = c0;
        float cE2 = c0 * c2 - s0 * s2;
        float cO  = c0 * c1 - s0 * s1;
        float sO  = s0 * c1 + c0 * s1;
        float cO2 = cO * c2 - sO * s2;
        float stp = 2.0f * c2;
        float accE = 0.0f, accO = 0.0f;
#pragma unroll
        for (int i = 0; i < 16; ++i) {
            accE = fmaf(sm.rx.fold[FIDX(n0 + 2 * i)],     cE, accE);
            accO = fmaf(sm.rx.fold[FIDX(n0 + 2 * i + 1)], cO, accO);
            float nE = fmaf(stp, cE2, -cE); cE = cE2; cE2 = nE;
            float nO = fmaf(stp, cO2, -cO); cO = cO2; cO2 = nO;
        }
        float acc = accE + accO;
        acc += __shfl_xor_sync(0xffffffffu, acc, 1);
        acc += __shfl_xor_sync(0xffffffffu, acc, 2);
        if (q == 0 && m < MMAX) {
            float last = sm.rx.row[128] * ((m & 1) ? -1.0f : 1.0f);
            g_rexf[combo][m][k] = (acc + last) * (2.0f * PI_F / NLON);
        }
    }
    gbar(2);

    // ================= Phase D: coefficients + partial loss (l >= m only) ===
    {
        int gw0 = bid * 8 + wid;
        for (int task = gw0; task < NB * LMAX * MMAX; task += 4096) {
            int b = task / (LMAX * MMAX);
            int r = task % (LMAX * MMAX);
            int l = r / MMAX;
            int m = r % MMAX;
            if (l < m) continue;
            const float* pw = g_pctw[m][l];
            const float* xp = g_rexf[b][m];
            const float* xt = g_rexf[2 + b][m];
            float pc = 0.0f, tc = 0.0f;
#pragma unroll
            for (int k = lane; k < NLAT; k += 32) {
                float w = pw[k];
                pc = fmaf(xp[k], w, pc);
                tc = fmaf(xt[k], w, tc);
            }
#pragma unroll
            for (int o = 16; o > 0; o >>= 1) {
                pc += __shfl_down_sync(0xffffffffu, pc, o);
                tc += __shfl_down_sync(0xffffffffu, tc, o);
            }
            if (lane == 0) {
                float d = pc - tc;
                float qd = (float)(LMAX - 1 - l);
                g_part[task] = d * d * expf(-qd * qd / (2.0f * LMAX * LMAX));
            }
        }
    }

    // ================= Final: last block reduces ============================
    __syncthreads();
    if (tid == 0) {
        __threadfence();
        int t = atomicAdd(&g_done, 1);
        s_last = (t == NBLK - 1) ? 1 : 0;
    }
    __syncthreads();
    if (s_last) {
        __threadfence();
        float acc = 0.0f;
        for (int i = tid; i < NB * LMAX * MMAX; i += 256) acc += g_part[i];
#pragma unroll
        for (int o = 16; o > 0; o >>= 1) acc += __shfl_down_sync(0xffffffffu, acc, o);
        if (lane == 0) sm.red[wid] = acc;
        __syncthreads();
        if (tid == 0) {
            float v = 0.0f;
            for (int j = 0; j < 8; ++j) v += sm.red[j];
            out[0] = v / (float)NB;
            g_done = 0;
            __threadfence();
        }
    }
}

extern "C" void kernel_launch(void* const* d_in, const int* in_sizes, int n_in,
                              void* d_out, int out_size) {
    const float* pred = (const float*)d_in[0];
    const float* tgt  = (const float*)d_in[1];
    k_mega<<<NBLK, 256>>>(pred, tgt, (float*)d_out);
}

// round 14
// speedup vs baseline: 1.0449x; 1.0449x over previous
#include <cuda_runtime.h>
#include <math.h>

#define NLAT 128
#define NLON 256
#define LMAX 50
#define MMAX 50
#define NPTS 2048
#define NB   2
#define MG   (NLAT*NLON)
#define NBT  32
#define NBP  64
#define NBINS (NBT*NBP)
#define PI_F 3.14159265358979323846f
#define H_BIN (PI_F/32.0f)
#define INVH  (32.0f/PI_F)
#define CAP   1536
#define NBLK  512
#define NGRP  16
#define GRPSZ (NBLK/NGRP)
#define NBAR  4
#define KINF  0x7F7FFFFFu
#define FIDX(n) ((n) + ((n) >> 5))

// ---- device scratch (globals; zero-init at load) ----
__device__ float4 g_sorted[4][NPTS];
__device__ int    g_binstart[4][NBINS + 1];
__device__ float  g_grid[4][MG];
__device__ float  g_pctw[MMAX][LMAX][NLAT];
__device__ float  g_rexf[4][MMAX][NLAT];
__device__ float  g_part[NB * LMAX * MMAX];   // l<m entries stay 0 forever
// hierarchical barrier state (all zero-init; each counter on own 128B line)
__device__ int    g_ga [NBAR][NGRP * 32];
__device__ int    g_gl [NBAR][NGRP * 32];
__device__ int    g_gg [NBAR * 32];
__device__ int    g_ggl[NBAR * 32];
__device__ int    g_rel[NBAR * 32];

union Smem {
    struct { float4 pts[NPTS]; int cnt[NBINS]; int wsum[8]; } prep;   // ~41KB
    struct { float4 cand[CAP]; int rowoff[12]; int rowsrc[12]; } it;  // ~24KB
    struct { float row[NLON]; float fold[136]; } rx;
    float red[64];
};

__device__ __forceinline__ void gbar(int id) {
    __syncthreads();
    if (threadIdx.x == 0) {
        int g = blockIdx.x & (NGRP - 1);          // spread co-arrivals across lines
        __threadfence();
        int a = atomicAdd(&g_ga[id][g * 32], 1);
        if (a == GRPSZ - 1) {
            int b = atomicAdd(&g_gg[id * 32], 1);
            if (b == NGRP - 1) {
                __threadfence();
                *(volatile int*)&g_rel[id * 32] = 1;
            }
        }
        while (*(volatile int*)&g_rel[id * 32] == 0) __nanosleep(64);
        __threadfence();
        // leave tree: reset for next graph replay
        int l = atomicAdd(&g_gl[id][g * 32], 1);
        if (l == GRPSZ - 1) {
            g_ga[id][g * 32] = 0;
            g_gl[id][g * 32] = 0;
            int bl = atomicAdd(&g_ggl[id * 32], 1);
            if (bl == NGRP - 1) {
                g_gg[id * 32]  = 0;
                g_ggl[id * 32] = 0;
                __threadfence();
                *(volatile int*)&g_rel[id * 32] = 0;
                __threadfence();
            }
        }
    }
    __syncthreads();
}

__device__ __forceinline__ int bin_of(float th, float ph) {
    int bt = (int)(th * INVH);
    int bp = (int)((ph + PI_F) * INVH);
    bt = min(max(bt, 0), NBT - 1);
    bp = min(max(bp, 0), NBP - 1);
    return bt * NBP + bp;
}

__device__ __forceinline__ void ins3(unsigned& k0, unsigned& k1, unsigned& k2, unsigned key) {
    unsigned t  = max(k0, key); k0 = min(k0, key);
    unsigned t2 = max(k1, t);   k1 = min(k1, t);
    k2 = min(k2, t2);
}

__global__ void __launch_bounds__(256, 4)
k_mega(const float* __restrict__ pred, const float* __restrict__ tgt,
       float* __restrict__ out) {
    __shared__ Smem sm;
    int bid  = blockIdx.x;
    int tid  = threadIdx.x;
    int lane = tid & 31;
    int wid  = tid >> 5;

    // ================= Phase A: prep (blocks 0-3) + pctw (4-28) =============
    if (bid < 4) {
        int cb = bid;
        int t = cb >> 1, b = cb & 1;
        const float* src = (t ? tgt : pred) + (size_t)b * NPTS * 3;
        for (int i = tid; i < NBINS; i += 256) sm.prep.cnt[i] = 0;
        __syncthreads();
        for (int i = tid; i < NPTS; i += 256) {
            float x = src[3 * i], y = src[3 * i + 1], z = src[3 * i + 2];
            float r   = sqrtf(x * x + y * y + z * z);
            float pn1 = sqrtf(y * y + z * z);
            float th  = acosf(fminf(fmaxf(x / r,   -1.0f), 1.0f));
            float a   = acosf(fminf(fmaxf(y / pn1, -1.0f), 1.0f));
            float ph  = ((z < 0.0f) ? (2.0f * PI_F - a) : a) - PI_F;
            float4 o; o.x = th; o.y = ph; o.z = r; o.w = 0.0f;
            sm.prep.pts[i] = o;
            atomicAdd(&sm.prep.cnt[bin_of(th, ph)], 1);
        }
        __syncthreads();
        int base = tid * 8;
        int local[8]; int s = 0;
#pragma unroll
        for (int j = 0; j < 8; ++j) { local[j] = s; s += sm.prep.cnt[base + j]; }
        int v = s;
#pragma unroll
        for (int o = 1; o < 32; o <<= 1) {
            int u = __shfl_up_sync(0xffffffffu, v, o);
            if (lane >= o) v += u;
        }
        if (lane == 31) sm.prep.wsum[wid] = v;
        __syncthreads();
        if (tid == 0) {
            int a = 0;
            for (int j = 0; j < 8; ++j) { int x = sm.prep.wsum[j]; sm.prep.wsum[j] = a; a += x; }
        }
        __syncthreads();
        int excl = v - s + sm.prep.wsum[wid];
#pragma unroll
        for (int j = 0; j < 8; ++j) {
            int off = excl + local[j];
            sm.prep.cnt[base + j] = off;
            g_binstart[cb][base + j] = off;
        }
        if (tid == 0) g_binstart[cb][NBINS] = NPTS;
        __syncthreads();
        for (int i = tid; i < NPTS; i += 256) {
            float4 p = sm.prep.pts[i];
            int pos = atomicAdd(&sm.prep.cnt[bin_of(p.x, p.y)], 1);
            g_sorted[cb][pos] = p;
        }
    } else if (bid < 29) {
        int m = (bid - 4) * 2 + (tid >> 7);
        int k = tid & 127;
        if (m < MMAX) {
            float theta = PI_F * (float)k / (float)(NLAT - 1);
            float cost  = cosf(theta);
            float sint  = sqrtf(fmaxf(1.0f - cost * cost, 0.0f));
            float c2  = cosf(2.0f * theta);
            float tc2 = 2.0f * c2;
            float cm1 = 1.0f, cj = c2;
            float v = 0.0f;
#pragma unroll 7
            for (int j = 1; j <= 63; ++j) {
                v = fmaf(cj, 2.0f / (4.0f * (float)j * (float)j - 1.0f), v);
                float cn = fmaf(tc2, cj, -cm1);
                cm1 = cj; cj = cn;
            }
            float w = (2.0f / 127.0f) * (1.0f - v);
            if (k == 0 || k == 127) w *= 0.5f;
            float pmm = sqrtf(1.0f / (4.0f * PI_F));
            for (int mm = 1; mm <= m; ++mm)
                pmm = -pmm * sqrtf((2.0f * mm + 1.0f) / (2.0f * mm)) * sint;
            for (int l = 0; l < m; ++l) g_pctw[m][l][k] = 0.0f;
            g_pctw[m][m][k] = pmm * w;
            if (m + 1 < LMAX) {
                float plm2 = pmm;
                float plm1 = sqrtf(2.0f * m + 3.0f) * cost * pmm;
                g_pctw[m][m + 1][k] = plm1 * w;
                for (int l = m + 2; l < LMAX; ++l) {
                    float fl = (float)l, fm = (float)m;
                    float a = sqrtf((4.0f * fl * fl - 1.0f) / (fl * fl - fm * fm));
                    float bq = sqrtf(((2.0f * fl + 1.0f) * (fl - 1.0f + fm) * (fl - 1.0f - fm)) /
                                     ((2.0f * fl - 3.0f) * (fl * fl - fm * fm)));
                    float pl = a * cost * plm1 - bq * plm2;
                    g_pctw[m][l][k] = pl * w;
                    plm2 = plm1; plm1 = pl;
                }
            }
        }
    }
    gbar(0);

    // ================= Phase B: 3-NN interp (512 tiles, unified halo) =======
    {
        int cb  = bid >> 7;
        int rem = bid & 127;
        int ty8 = rem >> 4, tx16 = rem & 15;
        int bt0 = ty8 * 4, bp0 = tx16 * 4;
        bool pole = (ty8 == 0) || (ty8 == 7);

        int irow = ty8 * 16 + (tid >> 4);
        int icol = tx16 * 16 + (tid & 15);
        float gth = (float)irow * (PI_F / NLAT);
        float gph = (float)(icol - NLAT) * (PI_F / NLAT);

        int ht0, ht1, hp0, hp1;
        if (pole) {
            ht0 = (ty8 == 0) ? 0 : 25;
            ht1 = (ty8 == 0) ? 6 : 31;
            hp0 = max(bp0 - 8, 0);
            hp1 = min(bp0 + 11, NBP - 1);
        } else {
            ht0 = max(bt0 - 2, 0); ht1 = min(bt0 + 5, NBT - 1);
            hp0 = max(bp0 - 2, 0); hp1 = min(bp0 + 5, NBP - 1);
        }
        int nrows = ht1 - ht0 + 1;
        if (tid < nrows) {
            int s = g_binstart[cb][(ht0 + tid) * NBP + hp0];
            int e = g_binstart[cb][(ht0 + tid) * NBP + hp1 + 1];
            sm.it.rowsrc[tid] = s;
            sm.it.rowoff[tid] = e - s;
        }
        __syncthreads();
        if (tid == 0) {
            int off = 0;
            for (int r = 0; r < nrows; ++r) {
                int len = sm.it.rowoff[r];
                sm.it.rowoff[r] = off;
                off += len;
            }
            sm.it.rowoff[nrows] = off;
        }
        __syncthreads();
        int ncand = sm.it.rowoff[nrows];
        if (ncand <= CAP) {
            for (int r = 0; r < nrows; ++r) {
                int o0 = sm.it.rowoff[r], len = sm.it.rowoff[r + 1] - o0, s0 = sm.it.rowsrc[r];
                for (int i = tid; i < len; i += 256) {
                    float4 p = g_sorted[cb][s0 + i];
                    p.w = __uint_as_float((unsigned)(s0 + i));
                    sm.it.cand[o0 + i] = p;
                }
            }
        }
        float mT = (ht0 > 0)       ? (gth - (float)ht0 * H_BIN)       : 1e9f;
        float mB = (ht1 < NBT - 1) ? ((float)(ht1 + 1) * H_BIN - gth) : 1e9f;
        float gpp = gph + PI_F;
        float mL = (hp0 > 0)       ? (gpp - (float)hp0 * H_BIN)       : 1e9f;
        float mR = (hp1 < NBP - 1) ? ((float)(hp1 + 1) * H_BIN - gpp) : 1e9f;
        float margin = fminf(fminf(mT, mB), fminf(mL, mR));
        __syncthreads();

        bool ovf = ncand > CAP;
        unsigned k0 = KINF, k1 = KINF, k2 = KINF;

        if (!ovf) {
#pragma unroll 4
            for (int i = 0; i < ncand; ++i) {
                float4 p = sm.it.cand[i];
                float dx = gth - p.x, dy = gph - p.y;
                float d = fmaf(dx, dx, dy * dy);
                unsigned key = (__float_as_uint(d) & 0xFFFFF800u) | __float_as_uint(p.w);
                ins3(k0, k1, k2, key);
            }
        }

        float d2k = __uint_as_float(k2 & 0xFFFFF800u);
        if (ovf || d2k > margin * margin) {
            int bt = min(irow >> 2, NBT - 1);
            int bp = min(icol >> 2, NBP - 1);
            int st0 = ovf ? 1000 : ht0, st1 = ovf ? -1 : ht1;
            int sp0 = ovf ? 1000 : hp0, sp1 = ovf ? -1 : hp1;
            for (int R = 0; R <= 64; ++R) {
                if (R > 0) {
                    float lb = (float)(R - 1) * H_BIN;
                    d2k = __uint_as_float(k2 & 0xFFFFF800u);
                    if (d2k <= lb * lb) break;
                }
                int t0 = max(bt - R, 0), t1 = min(bt + R, NBT - 1);
                int p0 = max(bp - R, 0), p1 = min(bp + R, NBP - 1);
                for (int y = t0; y <= t1; ++y) {
                    bool full = (R == 0) || (y == bt - R) || (y == bt + R);
                    int xs = full ? p0 : (bp - R);
                    int xe = full ? p1 : (bp + R);
                    int xstep = full ? 1 : (2 * R);
                    for (int x = xs; x <= xe; x += xstep) {
                        if (x < 0 || x > NBP - 1) continue;
                        if (y >= st0 && y <= st1 && x >= sp0 && x <= sp1) continue;
                        int bi = y * NBP + x;
                        int s0 = g_binstart[cb][bi], s1 = g_binstart[cb][bi + 1];
                        for (int i = s0; i < s1; ++i) {
                            float4 p = g_sorted[cb][i];
                            float dx = gth - p.x, dy = gph - p.y;
                            float d = fmaf(dx, dx, dy * dy);
                            unsigned key = (__float_as_uint(d) & 0xFFFFF800u) | (unsigned)i;
                            ins3(k0, k1, k2, key);
                        }
                    }
                }
            }
        }

        float4 q0 = g_sorted[cb][k0 & 0x7FFu];
        float4 q1 = g_sorted[cb][k1 & 0x7FFu];
        float4 q2 = g_sorted[cb][k2 & 0x7FFu];
        float dx, dy;
        dx = gth - q0.x; dy = gph - q0.y; float e0 = fmaf(dx, dx, dy * dy);
        dx = gth - q1.x; dy = gph - q1.y; float e1 = fmaf(dx, dx, dy * dy);
        dx = gth - q2.x; dy = gph - q2.y; float e2 = fmaf(dx, dx, dy * dy);
        float s = e0 + e1 + e2;
        g_grid[cb][irow * NLON + icol] = (e0 * q0.z + e1 * q1.z + e2 * q2.z) / s;
    }
    gbar(1);

    // ================= Phase C: DFT via fold + Chebyshev ====================
    {
        int combo = bid >> 7;
        int k     = bid & 127;
        sm.rx.row[tid] = g_grid[combo][k * NLON + tid];
        __syncthreads();
        if (tid == 0)            sm.rx.fold[FIDX(0)] = sm.rx.row[0];
        else if (tid < 128)      sm.rx.fold[FIDX(tid)] = sm.rx.row[tid] + sm.rx.row[256 - tid];
        __syncthreads();

        int m = tid >> 2, q = tid & 3;
        float am = (PI_F / 128.0f) * (float)m;
        int n0 = q * 32;
        float s0, c0, s1, c1;
        sincosf(am * (float)n0, &s0, &c0);
        sincosf(am, &s1, &c1);
        float c2 = fmaf(2.0f * c1, c1, -1.0f);
        float s2 = 2.0f * s1 * c1;
        float cE  = c0;
        float cE2 = c0 * c2 - s0 * s2;
        float cO  = c0 * c1 - s0 * s1;
        float sO  = s0 * c1 + c0 * s1;
        float cO2 = cO * c2 - sO * s2;
        float stp = 2.0f * c2;
        float accE = 0.0f, accO = 0.0f;
#pragma unroll
        for (int i = 0; i < 16; ++i) {
            accE = fmaf(sm.rx.fold[FIDX(n0 + 2 * i)],     cE, accE);
            accO = fmaf(sm.rx.fold[FIDX(n0 + 2 * i + 1)], cO, accO);
            float nE = fmaf(stp, cE2, -cE); cE = cE2; cE2 = nE;
            float nO = fmaf(stp, cO2, -cO); cO = cO2; cO2 = nO;
        }
        float acc = accE + accO;
        acc += __shfl_xor_sync(0xffffffffu, acc, 1);
        acc += __shfl_xor_sync(0xffffffffu, acc, 2);
        if (q == 0 && m < MMAX) {
            float last = sm.rx.row[128] * ((m & 1) ? -1.0f : 1.0f);
            g_rexf[combo][m][k] = (acc + last) * (2.0f * PI_F / NLON);
        }
    }
    gbar(2);

    // ================= Phase D: coefficients + partial loss (l >= m only) ===
    {
        int gw0 = bid * 8 + wid;
        for (int task = gw0; task < NB * LMAX * MMAX; task += 4096) {
            int b = task / (LMAX * MMAX);
            int r = task % (LMAX * MMAX);
            int l = r / MMAX;
            int m = r % MMAX;
            if (l < m) continue;
            const float* pw = g_pctw[m][l];
            const float* xp = g_rexf[b][m];
            const float* xt = g_rexf[2 + b][m];
            float pc = 0.0f, tc = 0.0f;
#pragma unroll
            for (int k = lane; k < NLAT; k += 32) {
                float w = pw[k];
                pc = fmaf(xp[k], w, pc);
                tc = fmaf(xt[k], w, tc);
            }
#pragma unroll
            for (int o = 16; o > 0; o >>= 1) {
                pc += __shfl_down_sync(0xffffffffu, pc, o);
                tc += __shfl_down_sync(0xffffffffu, tc, o);
            }
            if (lane == 0) {
                float d = pc - tc;
                float qd = (float)(LMAX - 1 - l);
                g_part[task] = d * d * expf(-qd * qd / (2.0f * LMAX * LMAX));
            }
        }
    }
    gbar(3);

    // ================= Final: block 0 reduces ===============================
    if (bid == 0) {
        float acc = 0.0f;
        for (int i = tid; i < NB * LMAX * MMAX; i += 256) acc += g_part[i];
#pragma unroll
        for (int o = 16; o > 0; o >>= 1) acc += __shfl_down_sync(0xffffffffu, acc, o);
        if (lane == 0) sm.red[wid] = acc;
        __syncthreads();
        if (tid == 0) {
            float v = 0.0f;
            for (int j = 0; j < 8; ++j) v += sm.red[j];
            out[0] = v / (float)NB;
        }
    }
}

extern "C" void kernel_launch(void* const* d_in, const int* in_sizes, int n_in,
                              void* d_out, int out_size) {
    const float* pred = (const float*)d_in[0];
    const float* tgt  = (const float*)d_in[1];
    k_mega<<<NBLK, 256>>>(pred, tgt, (float*)d_out);
}

// round 16
// speedup vs baseline: 1.3626x; 1.3040x over previous
#include <cuda_runtime.h>
#include <math.h>

#define NLAT 128
#define NLON 256
#define LMAX 50
#define MMAX 50
#define NPTS 2048
#define NB   2
#define MG   (NLAT*NLON)
#define NBT  32
#define NPH  32
#define NBINS2 (NBT*NPH)
#define PI_F 3.14159265358979323846f
#define H_BIN (PI_F/32.0f)
#define W_PH  (PI_F/16.0f)
#define INVH  (32.0f/PI_F)
#define INVW  (16.0f/PI_F)
#define NBLK  512
#define KINF  0x7F7FFFFFu
#define FIDX(n) ((n) + ((n) >> 5))

// ---- device scratch (globals; zero-init at load) ----
__device__ float  g_grid[4][MG];
__device__ float  g_pctw[MMAX][LMAX][NLAT];
__device__ float  g_rexf[4][MMAX][NLAT];
__device__ float  g_part[NB * LMAX * MMAX];   // l<m entries stay 0 forever
__device__ int    g_barc[5 * 64];             // ids 0-3: per-combo; 4: global
__device__ int    g_done;

struct SmemT {
    float4 pts[NPTS];                          // sorted points (th,ph,r,-) 32KB
    union {
        struct { int bstart[NBINS2 + 1]; int off[NBINS2]; int wsum[8]; } ab;
        struct { float row[NLON]; float fold[136]; } rx;
        float red[64];
    } u;
    float sa[LMAX], sb[LMAX];
    int last;
};

__device__ __forceinline__ void gbar(int id, int count) {
    __syncthreads();
    if (threadIdx.x == 0) {
        __threadfence();
        atomicAdd(&g_barc[id * 64], 1);
        while (*(volatile int*)&g_barc[id * 64] < count) __nanosleep(64);
        __threadfence();
        int l = atomicAdd(&g_barc[id * 64 + 32], 1);
        if (l == count - 1) {
            g_barc[id * 64]      = 0;
            g_barc[id * 64 + 32] = 0;
            __threadfence();
        }
    }
    __syncthreads();
}

__device__ __forceinline__ void ins3(unsigned& k0, unsigned& k1, unsigned& k2, unsigned key) {
    unsigned t  = max(k0, key); k0 = min(k0, key);
    unsigned t2 = max(k1, t);   k1 = min(k1, t);
    k2 = min(k2, t2);
}

__global__ void __launch_bounds__(256, 4)
k_mega(const float* __restrict__ pred, const float* __restrict__ tgt,
       float* __restrict__ out) {
    __shared__ SmemT sm;
    int bid  = blockIdx.x;
    int tid  = threadIdx.x;
    int lane = tid & 31;
    int wid  = tid >> 5;
    int cb   = bid >> 7;

    // ===== Phase A: redundant per-block convert + counting-sort into SMEM ===
    {
        const float* src = ((cb >> 1) ? tgt : pred) + (size_t)(cb & 1) * NPTS * 3;
        for (int i = tid; i < NBINS2; i += 256) sm.u.ab.off[i] = 0;
        __syncthreads();
        float pth[8], pph[8], prr[8];
#pragma unroll
        for (int j = 0; j < 8; ++j) {
            int i = j * 256 + tid;
            float x = src[3 * i], y = src[3 * i + 1], z = src[3 * i + 2];
            float r   = sqrtf(x * x + y * y + z * z);
            float pn1 = sqrtf(y * y + z * z);
            float th  = acosf(fminf(fmaxf(x / r,   -1.0f), 1.0f));
            float a   = acosf(fminf(fmaxf(y / pn1, -1.0f), 1.0f));
            float ph  = ((z < 0.0f) ? (2.0f * PI_F - a) : a) - PI_F;
            pth[j] = th; pph[j] = ph; prr[j] = r;
            int bt = min(max((int)(th * INVH), 0), NBT - 1);
            int bp = min(max((int)((ph + PI_F) * INVW), 0), NPH - 1);
            atomicAdd(&sm.u.ab.off[bt * NPH + bp], 1);
        }
        __syncthreads();
        // exclusive scan over 1024 bins (4/thread)
        int base = tid * 4;
        int loc[4]; int s = 0;
#pragma unroll
        for (int j = 0; j < 4; ++j) { loc[j] = s; s += sm.u.ab.off[base + j]; }
        int v = s;
#pragma unroll
        for (int o = 1; o < 32; o <<= 1) {
            int u = __shfl_up_sync(0xffffffffu, v, o);
            if (lane >= o) v += u;
        }
        if (lane == 31) sm.u.ab.wsum[wid] = v;
        __syncthreads();
        if (tid == 0) {
            int a = 0;
            for (int j = 0; j < 8; ++j) { int x = sm.u.ab.wsum[j]; sm.u.ab.wsum[j] = a; a += x; }
        }
        __syncthreads();
        int excl = v - s + sm.u.ab.wsum[wid];
#pragma unroll
        for (int j = 0; j < 4; ++j) {
            int st = excl + loc[j];
            sm.u.ab.bstart[base + j] = st;
            sm.u.ab.off[base + j]    = st;
        }
        if (tid == 0) sm.u.ab.bstart[NBINS2] = NPTS;
        __syncthreads();
#pragma unroll
        for (int j = 0; j < 8; ++j) {
            int bt = min(max((int)(pth[j] * INVH), 0), NBT - 1);
            int bp = min(max((int)((pph[j] + PI_F) * INVW), 0), NPH - 1);
            int pos = atomicAdd(&sm.u.ab.off[bt * NPH + bp], 1);
            sm.pts[pos] = make_float4(pth[j], pph[j], prr[j], 0.0f);
        }
        __syncthreads();
    }

    // ===== pctw (blocks 0-49 only, one m each; parallel coefs) ==============
    if (bid < MMAX) {
        int m = bid;
        if (tid >= 128 && tid < 128 + LMAX) {
            int l = tid - 128;
            if (l >= m + 2) {
                float fl = (float)l, fm = (float)m;
                sm.sa[l] = sqrtf((4.0f * fl * fl - 1.0f) / (fl * fl - fm * fm));
                sm.sb[l] = sqrtf(((2.0f * fl + 1.0f) * (fl - 1.0f + fm) * (fl - 1.0f - fm)) /
                                 ((2.0f * fl - 3.0f) * (fl * fl - fm * fm)));
            }
        }
        float prod = 1.0f;
        for (int mm = 1; mm <= m; ++mm) {
            float f = 2.0f * (float)mm;
            prod *= __fdividef(f + 1.0f, f);
        }
        __syncthreads();
        if (tid < 128) {
            int k = tid;
            float theta = PI_F * (float)k / (float)(NLAT - 1);
            float cost  = cosf(theta);
            float sint  = sqrtf(fmaxf(1.0f - cost * cost, 0.0f));
            // Clenshaw-Curtis weight via Chebyshev recurrence
            float c2  = cosf(2.0f * theta);
            float tc2 = 2.0f * c2;
            float cm1 = 1.0f, cj = c2;
            float v = 0.0f;
#pragma unroll 7
            for (int j = 1; j <= 63; ++j) {
                v = fmaf(cj, 2.0f / (4.0f * (float)j * (float)j - 1.0f), v);
                float cn = fmaf(tc2, cj, -cm1);
                cm1 = cj; cj = cn;
            }
            float w = (2.0f / 127.0f) * (1.0f - v);
            if (k == 0 || k == 127) w *= 0.5f;
            float pmag = sqrtf(prod / (4.0f * PI_F));
            float pmm;
            if (m == 0) pmm = pmag;
            else if (sint > 0.0f)
                pmm = pmag * ((m & 1) ? -1.0f : 1.0f) * exp2f((float)m * log2f(sint));
            else pmm = 0.0f;
            for (int l = 0; l < m; ++l) g_pctw[m][l][k] = 0.0f;
            g_pctw[m][m][k] = pmm * w;
            if (m + 1 < LMAX) {
                float plm2 = pmm;
                float plm1 = sqrtf(2.0f * m + 3.0f) * cost * pmm;
                g_pctw[m][m + 1][k] = plm1 * w;
                for (int l = m + 2; l < LMAX; ++l) {
                    float pl = sm.sa[l] * cost * plm1 - sm.sb[l] * plm2;
                    g_pctw[m][l][k] = pl * w;
                    plm2 = plm1; plm1 = pl;
                }
            }
        }
        __syncthreads();
    }

    // ===== Phase B: 3-NN interp from LOCAL sorted smem (per-warp windows) ===
    {
        int rem = bid & 127;
        int ty8 = rem >> 4, tx16 = rem & 15;
        int irow = ty8 * 16 + (tid >> 4);
        int icol = tx16 * 16 + (tid & 15);
        float gth = (float)irow * (PI_F / NLAT);
        float gph = (float)(icol - NLAT) * (PI_F / NLAT);
        float gpp = gph + PI_F;

        int btw = ty8 * 4 + (wid >> 1);                 // warp's theta bin
        bool np = (btw <= 2) || (btw >= NBT - 3);
        int yr = np ? 4 : 2;
        int yw0 = max(btw - yr, 0), yw1 = min(btw + yr, NBT - 1);
        int bpw = tx16 * 2;
        int xr = np ? 4 : 1;
        int xw0 = max(bpw - xr, 0), xw1 = min(bpw + 1 + xr, NPH - 1);

        float mT = (yw0 == 0)       ? 1e9f : gth - (float)yw0 * H_BIN;
        float mB = (yw1 == NBT - 1) ? 1e9f : (float)(yw1 + 1) * H_BIN - gth;
        float mL = (xw0 == 0)       ? 1e9f : gpp - (float)xw0 * W_PH;
        float mR = (xw1 == NPH - 1) ? 1e9f : (float)(xw1 + 1) * W_PH - gpp;
        float margin = fminf(fminf(mT, mB), fminf(mL, mR));

        unsigned k0 = KINF, k1 = KINF, k2 = KINF;
        for (int y = yw0; y <= yw1; ++y) {
            int s = sm.u.ab.bstart[y * NPH + xw0];
            int e = sm.u.ab.bstart[y * NPH + xw1 + 1];
#pragma unroll 4
            for (int i = s; i < e; ++i) {
                float4 p = sm.pts[i];                    // warp-broadcast LDS
                float dx = gth - p.x, dy = gph - p.y;
                float d = fmaf(dx, dx, dy * dy);
                unsigned key = (__float_as_uint(d) & 0xFFFFF800u) | (unsigned)i;
                ins3(k0, k1, k2, key);
            }
        }

        float d2k = __uint_as_float(k2 & 0xFFFFF800u);
        if (d2k > margin * margin) {
            // ring fallback over smem bins, skipping the scanned rect
            int cbt = min(irow >> 2, NBT - 1);
            int cbp = min(((icol >> 3)), NPH - 1);       // icol/8: phi bin of width 8 cols
            for (int R = 0; R <= 32; ++R) {
                if (R > 0) {
                    float lb = (float)(R - 1) * H_BIN;
                    d2k = __uint_as_float(k2 & 0xFFFFF800u);
                    if (d2k <= lb * lb) break;
                }
                int t0 = max(cbt - R, 0), t1 = min(cbt + R, NBT - 1);
                int p0 = max(cbp - R, 0), p1 = min(cbp + R, NPH - 1);
                for (int y = t0; y <= t1; ++y) {
                    bool full = (R == 0) || (y == cbt - R) || (y == cbt + R);
                    int xs = full ? p0 : (cbp - R);
                    int xe = full ? p1 : (cbp + R);
                    int xstep = full ? 1 : (2 * R);
                    for (int x = xs; x <= xe; x += xstep) {
                        if (x < 0 || x > NPH - 1) continue;
                        if (y >= yw0 && y <= yw1 && x >= xw0 && x <= xw1) continue;
                        int bi = y * NPH + x;
                        int s0 = sm.u.ab.bstart[bi], s1 = sm.u.ab.bstart[bi + 1];
                        for (int i = s0; i < s1; ++i) {
                            float4 p = sm.pts[i];
                            float dx = gth - p.x, dy = gph - p.y;
                            float d = fmaf(dx, dx, dy * dy);
                            unsigned key = (__float_as_uint(d) & 0xFFFFF800u) | (unsigned)i;
                            ins3(k0, k1, k2, key);
                        }
                    }
                }
            }
        }

        float4 q0 = sm.pts[k0 & 0x7FFu];
        float4 q1 = sm.pts[k1 & 0x7FFu];
        float4 q2 = sm.pts[k2 & 0x7FFu];
        float dx, dy;
        dx = gth - q0.x; dy = gph - q0.y; float e0 = fmaf(dx, dx, dy * dy);
        dx = gth - q1.x; dy = gph - q1.y; float e1 = fmaf(dx, dx, dy * dy);
        dx = gth - q2.x; dy = gph - q2.y; float e2 = fmaf(dx, dx, dy * dy);
        float s = e0 + e1 + e2;
        g_grid[cb][irow * NLON + icol] = (e0 * q0.z + e1 * q1.z + e2 * q2.z) / s;
    }
    gbar(cb, 128);                 // per-combo: g_grid[cb] complete

    // ===== Phase C: DFT via fold + Chebyshev (block = grid row of own cb) ===
    {
        int k = bid & 127;
        sm.u.rx.row[tid] = g_grid[cb][k * NLON + tid];
        __syncthreads();
        if (tid == 0)       sm.u.rx.fold[FIDX(0)]   = sm.u.rx.row[0];
        else if (tid < 128) sm.u.rx.fold[FIDX(tid)] = sm.u.rx.row[tid] + sm.u.rx.row[256 - tid];
        __syncthreads();

        int m = tid >> 2, q = tid & 3;
        float am = (PI_F / 128.0f) * (float)m;
        int n0 = q * 32;
        float s0, c0, s1, c1;
        sincosf(am * (float)n0, &s0, &c0);
        sincosf(am, &s1, &c1);
        float c2 = fmaf(2.0f * c1, c1, -1.0f);
        float s2 = 2.0f * s1 * c1;
        float cE  = c0;
        float cE2 = c0 * c2 - s0 * s2;
        float cO  = c0 * c1 - s0 * s1;
        float sO  = s0 * c1 + c0 * s1;
        float cO2 = cO * c2 - sO * s2;
        float stp = 2.0f * c2;
        float accE = 0.0f, accO = 0.0f;
#pragma unroll
        for (int i = 0; i < 16; ++i) {
            accE = fmaf(sm.u.rx.fold[FIDX(n0 + 2 * i)],     cE, accE);
            accO = fmaf(sm.u.rx.fold[FIDX(n0 + 2 * i + 1)], cO, accO);
            float nE = fmaf(stp, cE2, -cE); cE = cE2; cE2 = nE;
            float nO = fmaf(stp, cO2, -cO); cO = cO2; cO2 = nO;
        }
        float acc = accE + accO;
        acc += __shfl_xor_sync(0xffffffffu, acc, 1);
        acc += __shfl_xor_sync(0xffffffffu, acc, 2);
        if (q == 0 && m < MMAX) {
            float last = sm.u.rx.row[128] * ((m & 1) ? -1.0f : 1.0f);
            g_rexf[cb][m][k] = (acc + last) * (2.0f * PI_F / NLON);
        }
    }
    gbar(4, NBLK);                 // global: all rexf + pctw visible

    // ===== Phase D: coefficients + partial loss (l >= m only) ===============
    {
        int gw0 = bid * 8 + wid;
        for (int task = gw0; task < NB * LMAX * MMAX; task += 4096) {
            int b = task / (LMAX * MMAX);
            int r = task % (LMAX * MMAX);
            int l = r / MMAX;
            int m = r % MMAX;
            if (l < m) continue;
            const float* pw = g_pctw[m][l];
            const float* xp = g_rexf[b][m];
            const float* xt = g_rexf[2 + b][m];
            float pc = 0.0f, tc = 0.0f;
#pragma unroll
            for (int k = lane; k < NLAT; k += 32) {
                float w = pw[k];
                pc = fmaf(xp[k], w, pc);
                tc = fmaf(xt[k], w, tc);
            }
#pragma unroll
            for (int o = 16; o > 0; o >>= 1) {
                pc += __shfl_down_sync(0xffffffffu, pc, o);
                tc += __shfl_down_sync(0xffffffffu, tc, o);
            }
            if (lane == 0) {
                float d = pc - tc;
                float qd = (float)(LMAX - 1 - l);
                g_part[task] = d * d * expf(-qd * qd / (2.0f * LMAX * LMAX));
            }
        }
    }

    // ===== Final: last-done block reduces ===================================
    __syncthreads();
    if (tid == 0) {
        __threadfence();
        int t = atomicAdd(&g_done, 1);
        sm.last = (t == NBLK - 1) ? 1 : 0;
    }
    __syncthreads();
    if (sm.last) {
        __threadfence();
        float acc = 0.0f;
        for (int i = tid; i < NB * LMAX * MMAX; i += 256) acc += g_part[i];
#pragma unroll
        for (int o = 16; o > 0; o >>= 1) acc += __shfl_down_sync(0xffffffffu, acc, o);
        if (lane == 0) sm.u.red[wid] = acc;
        __syncthreads();
        if (tid == 0) {
            float v = 0.0f;
            for (int j = 0; j < 8; ++j) v += sm.u.red[j];
            out[0] = v / (float)NB;
            g_done = 0;
            __threadfence();
        }
    }
}

extern "C" void kernel_launch(void* const* d_in, const int* in_sizes, int n_in,
                              void* d_out, int out_size) {
    const float* pred = (const float*)d_in[0];
    const float* tgt  = (const float*)d_in[1];
    k_mega<<<NBLK, 256>>>(pred, tgt, (float*)d_out);
}